// round 6
// baseline (speedup 1.0000x reference)
#include <cuda_runtime.h>
#include <cuda_bf16.h>
#include <cstdint>

#define LL 65536
#define DD 256
#define CC 1024     // chunks == blocks (must fit in one wave: 1024 <= 148*8)
#define RR 64       // rows per chunk
#define NSEG 32     // scan blocks
#define SEGC 32     // chunks per segment

#define NEG_INF __int_as_float(0xff800000)

// ---- scratch (device globals) ----
__device__ float g_M[CC], g_U[CC];
__device__ float g_W[CC * DD];
__device__ float g_Mp[CC], g_Up[CC];
__device__ float g_Wp[CC * DD];       // segment-local exclusive prefix (ref Mp_c)
__device__ float g_seg[NSEG * DD];    // segment aggregates
__device__ unsigned g_bar1, g_bar2;   // monotonic barrier counters (epoch-safe)

__device__ __forceinline__ void grid_barrier(unsigned* ctr, int t) {
    __syncthreads();
    if (t == 0) {
        __threadfence();
        unsigned old = atomicAdd(ctr, 1u);
        unsigned target = (old / CC + 1u) * CC;   // end of this replay's epoch
        unsigned v;
        for (;;) {
            asm volatile("ld.global.acquire.gpu.u32 %0, [%1];" : "=r"(v) : "l"(ctr));
            if (v >= target) break;
            __nanosleep(128);
        }
    }
    __syncthreads();
}

__global__ __launch_bounds__(256, 8) void k_fused(const float* __restrict__ K,
                                                  const float* __restrict__ V,
                                                  const float* __restrict__ q,
                                                  float* __restrict__ out) {
    __shared__ __align__(16) float q_sh[DD];
    __shared__ __align__(16) float wpart[4][DD];   // 4KB (float4 accessed)
    __shared__ float s_sh[RR], e_sh[RR], m_sh[RR];
    __shared__ float a_sh[RR], b_sh[RR], sA[RR], sB[RR], inv_sh[RR];
    __shared__ float red_sh[8];
    __shared__ float Mbc;
    __shared__ float Pm[CC];           // 4KB  (scan blocks)
    __shared__ float As[CC], Bs[CC];   // 8KB  (block 0 pair scan)

    const int c = blockIdx.x;
    const int t = threadIdx.x;
    const int lane = t & 31;
    const int wid = t >> 5;

    // ================= Phase A: s = K·q ; chunk (M,U,W) =================
    q_sh[t] = q[t];
    __syncthreads();

    const float4* q4 = reinterpret_cast<const float4*>(q_sh);
    const float4* K4 = reinterpret_cast<const float4*>(K) + (size_t)c * RR * 64;

    float4 qa = q4[lane], qb = q4[32 + lane];
#pragma unroll
    for (int k = 0; k < RR / 8; k++) {
        int r = wid * (RR / 8) + k;
        float4 ka = __ldcs(&K4[r * 64 + lane]);      // K read-once: evict-first
        float4 kb = __ldcs(&K4[r * 64 + 32 + lane]);
        float p = ka.x * qa.x + ka.y * qa.y + ka.z * qa.z + ka.w * qa.w
                + kb.x * qb.x + kb.y * qb.y + kb.z * qb.z + kb.w * qb.w;
#pragma unroll
        for (int o = 16; o; o >>= 1) p += __shfl_xor_sync(0xffffffffu, p, o);
        if (lane == 0) s_sh[r] = p;
    }
    __syncthreads();

    // chunk max
    float m = (t < RR) ? s_sh[t] : NEG_INF;
#pragma unroll
    for (int o = 16; o; o >>= 1) m = fmaxf(m, __shfl_xor_sync(0xffffffffu, m, o));
    if (lane == 0) red_sh[wid] = m;
    __syncthreads();
    if (t == 0) {
        float mm = NEG_INF;
#pragma unroll
        for (int w = 0; w < 8; w++) mm = fmaxf(mm, red_sh[w]);
        Mbc = mm;
    }
    __syncthreads();
    const float M = Mbc;

    if (t < RR) e_sh[t] = __expf(s_sh[t] - M);
    __syncthreads();

    // U
    float uu = (t < RR) ? e_sh[t] : 0.f;
#pragma unroll
    for (int o = 16; o; o >>= 1) uu += __shfl_xor_sync(0xffffffffu, uu, o);
    __syncthreads();
    if (lane == 0) red_sh[wid] = uu;
    __syncthreads();
    if (t == 0) {
        float U = 0.f;
#pragma unroll
        for (int w = 0; w < 8; w++) U += red_sh[w];
        g_M[c] = M;
        g_U[c] = U;
    }

    // W[d] = sum_i e_i * V[i][d]   (V default policy -> L2 resident for Phase C)
    {
        const int grp = t >> 6;
        const int j = t & 63;
        const float4* V4 = reinterpret_cast<const float4*>(V) + (size_t)c * RR * 64;
        float4 acc = make_float4(0.f, 0.f, 0.f, 0.f);
#pragma unroll
        for (int i = grp; i < RR; i += 4) {
            float e = e_sh[i];
            float4 v = V4[i * 64 + j];
            acc.x += e * v.x; acc.y += e * v.y; acc.z += e * v.z; acc.w += e * v.w;
        }
        reinterpret_cast<float4*>(wpart[grp])[j] = acc;
    }
    __syncthreads();
    g_W[(size_t)c * DD + t] = wpart[0][t] + wpart[1][t] + wpart[2][t] + wpart[3][t];

    // in-chunk inclusive prefix max (no global info needed; overlap with stragglers)
    if (t < RR) m_sh[t] = s_sh[t];
    __syncthreads();
    {
        float cmx = (t < RR) ? m_sh[t] : NEG_INF;
#pragma unroll
        for (int off = 1; off < RR; off <<= 1) {
            float v = NEG_INF;
            if (t < RR && t >= off) v = m_sh[t - off];
            __syncthreads();
            if (t < RR) { cmx = fmaxf(cmx, v); m_sh[t] = cmx; }
            __syncthreads();
        }
    }

    // ================= Barrier 1 =================
    grid_barrier(&g_bar1, t);

    // ================= Phase B: scan blocks only =================
    if (c < NSEG) {
        // global prefix max over chunk maxima (redundant per scan block)
        float mv[4], cm[4];
#pragma unroll
        for (int r = 0; r < 4; r++) {
            mv[r] = __ldcg(&g_M[t + r * 256]);
            Pm[t + r * 256] = mv[r];
            cm[r] = mv[r];
        }
        __syncthreads();
        for (int off = 1; off < CC; off <<= 1) {
            float v[4];
#pragma unroll
            for (int r = 0; r < 4; r++) {
                int i = t + r * 256;
                v[r] = (i >= off) ? Pm[i - off] : NEG_INF;
            }
            __syncthreads();
#pragma unroll
            for (int r = 0; r < 4; r++) {
                cm[r] = fmaxf(cm[r], v[r]);
                Pm[t + r * 256] = cm[r];
            }
            __syncthreads();
        }

        // block 0: scalar u pair-scan, publish g_Mp / g_Up
        if (c == 0) {
            float ca[4], cb[4];
#pragma unroll
            for (int r = 0; r < 4; r++) {
                int i = t + r * 256;
                float Minc = Pm[i];
                float Mp = (i == 0) ? NEG_INF : Pm[i - 1];
                float a = (i == 0) ? 0.f : __expf(Mp - Minc);
                float g = __expf(mv[r] - Minc);
                ca[r] = a;
                cb[r] = __ldcg(&g_U[i]) * g;
                As[i] = ca[r];
                Bs[i] = cb[r];
                g_Mp[i] = Mp;
            }
            __syncthreads();
            for (int off = 1; off < CC; off <<= 1) {
                float va[4], vb[4];
#pragma unroll
                for (int r = 0; r < 4; r++) {
                    int i = t + r * 256;
                    if (i >= off) { va[r] = As[i - off]; vb[r] = Bs[i - off]; }
                    else          { va[r] = 1.f;         vb[r] = 0.f; }
                }
                __syncthreads();
#pragma unroll
                for (int r = 0; r < 4; r++) {
                    int i = t + r * 256;
                    cb[r] = fmaf(vb[r], ca[r], cb[r]);
                    ca[r] = va[r] * ca[r];
                    As[i] = ca[r];
                    Bs[i] = cb[r];
                }
                __syncthreads();
            }
#pragma unroll
            for (int r = 0; r < 4; r++) {
                int i = t + r * 256;
                g_Up[i] = (i == 0) ? 0.f : Bs[i - 1];
            }
        }

        // segment W-scan with 8-deep load pipeline (alpha/gamma from Pm)
        {
            const int j0 = c * SEGC;
            const float* Wsrc = g_W + (size_t)j0 * DD + t;
            float* Wdst = g_Wp + (size_t)j0 * DD + t;

            float buf[8];
#pragma unroll
            for (int j = 0; j < 8; j++) buf[j] = __ldcg(&Wsrc[(size_t)j * DD]);

            float w = 0.f;
            for (int jb = 0; jb < SEGC; jb += 8) {
                float nbuf[8];
#pragma unroll
                for (int j = 0; j < 8; j++)
                    nbuf[j] = (jb + 8 < SEGC) ? __ldcg(&Wsrc[(size_t)(jb + 8 + j) * DD]) : 0.f;
#pragma unroll
                for (int j = 0; j < 8; j++) {
                    int cj = j0 + jb + j;
                    float Minc = Pm[cj];
                    float Mpj = (cj == 0) ? NEG_INF : Pm[cj - 1];
                    float al = (cj == 0) ? 0.f : __expf(Mpj - Minc);
                    float ga = __expf(__ldcg(&g_M[cj]) - Minc);
                    Wdst[(size_t)(jb + j) * DD] = w;
                    w = fmaf(w, al, buf[j] * ga);
                }
#pragma unroll
                for (int j = 0; j < 8; j++) buf[j] = nbuf[j];
            }
            g_seg[c * DD + t] = w;
        }
    }

    // ================= Barrier 2 =================
    grid_barrier(&g_bar2, t);

    // ================= Phase C: per-row recurrence, stream V -> out =================
    const float Mp_c = __ldcg(&g_Mp[c]);
    const float Up_c = __ldcg(&g_Up[c]);

    float cA = 1.f, cB = 0.f;
    if (t < RR) {
        float mi = fmaxf(m_sh[t], Mp_c);
        float mp = (t == 0) ? Mp_c : fmaxf(m_sh[t - 1], Mp_c);
        float a = __expf(mp - mi);
        float bb = __expf(s_sh[t] - mi);
        a_sh[t] = a; b_sh[t] = bb;
        cA = a; cB = bb;
        sA[t] = a; sB[t] = bb;
    }
    __syncthreads();

    // pair scan: u_i = B_i + A_i * Up_c
#pragma unroll
    for (int off = 1; off < RR; off <<= 1) {
        float va = 1.f, vb = 0.f;
        if (t < RR && t >= off) { va = sA[t - off]; vb = sB[t - off]; }
        __syncthreads();
        if (t < RR) {
            cB = fmaf(vb, cA, cB);
            cA = va * cA;
            sA[t] = cA; sB[t] = cB;
        }
        __syncthreads();
    }
    if (t < RR) inv_sh[t] = 1.0f / fmaf(cA, Up_c, cB);
    __syncthreads();

    // seed: segment-local exclusive prefix + segment carry
    const int seg = c / SEGC;
    float w = __ldcg(&g_Wp[(size_t)c * DD + t]);
    if (seg > 0) {
        float car = 0.f;
        for (int sb = 0; sb < seg; sb++) {
            float sc = (sb == 0) ? 0.f
                     : __expf(__ldcg(&g_Mp[sb * SEGC]) - __ldcg(&g_Mp[(sb + 1) * SEGC]));
            car = fmaf(car, sc, __ldcg(&g_seg[sb * DD + t]));
        }
        w = fmaf(car, __expf(__ldcg(&g_Mp[seg * SEGC]) - Mp_c), w);
    }

    const float* Vb = V + (size_t)c * RR * DD + t;
    float* Ob = out + (size_t)c * RR * DD + t;

    float cur[8];
#pragma unroll
    for (int j = 0; j < 8; j++) cur[j] = Vb[(size_t)j * DD];

    for (int ib = 0; ib < RR; ib += 8) {
        float nxt[8];
#pragma unroll
        for (int j = 0; j < 8; j++)
            nxt[j] = (ib + 8 < RR) ? Vb[(size_t)(ib + 8 + j) * DD] : 0.f;
#pragma unroll
        for (int j = 0; j < 8; j++) {
            int i = ib + j;
            w = fmaf(w, a_sh[i], b_sh[i] * cur[j]);
            __stcs(&Ob[(size_t)i * DD], w * inv_sh[i]);
        }
#pragma unroll
        for (int j = 0; j < 8; j++) cur[j] = nxt[j];
    }
}

// ============================================================
extern "C" void kernel_launch(void* const* d_in, const int* in_sizes, int n_in,
                              void* d_out, int out_size) {
    const float* K = (const float*)d_in[0];
    const float* V = (const float*)d_in[1];
    const float* q = (const float*)d_in[2];
    float* out = (float*)d_out;

    k_fused<<<CC, 256>>>(K, V, q, out);
}